// round 13
// baseline (speedup 1.0000x reference)
#include <cuda_runtime.h>
#include <cuda_bf16.h>

// Problem constants (fixed by setup_inputs): B=4, H=16, N=4096, d=128.
#define BH_      64
#define NSEQ_    4096
#define DIM_     128
#define BR_      64          // Q rows per CTA
#define BC_      64          // KV rows per tile
#define KSTRIDE  132         // floats per K smem row (pad 4)
#define VSTRIDE  136         // floats per V smem row (pad 8)
#define NTHREADS 128         // 4 warps, each owns 16 Q rows
#define NTILES   (NSEQ_ / BC_)

// Pre-converted (tf32-rna) copies of K and V. 128MB each — static device scratch.
__device__ float g_kc[(size_t)BH_ * NSEQ_ * DIM_];
__device__ float g_vc[(size_t)BH_ * NSEQ_ * DIM_];

__device__ __forceinline__ unsigned tf32_rna(float x) {
    unsigned u;
    asm("cvt.rna.tf32.f32 %0, %1;" : "=r"(u) : "f"(x));
    return u;
}

__device__ __forceinline__ void mma_tf32(float& d0, float& d1, float& d2, float& d3,
                                         unsigned a0, unsigned a1, unsigned a2, unsigned a3,
                                         unsigned b0, unsigned b1) {
    asm("mma.sync.aligned.m16n8k8.row.col.f32.tf32.tf32.f32 "
        "{%0,%1,%2,%3}, {%4,%5,%6,%7}, {%8,%9}, {%0,%1,%2,%3};\n"
        : "+f"(d0), "+f"(d1), "+f"(d2), "+f"(d3)
        : "r"(a0), "r"(a1), "r"(a2), "r"(a3), "r"(b0), "r"(b1));
}

// ---------------- pre-pass: rna-convert one array (float4 grid-stride) ----------------
__global__ void conv_tf32_kernel(const float* __restrict__ src, float* __restrict__ dst) {
    const size_t n4 = (size_t)BH_ * NSEQ_ * DIM_ / 4;
    for (size_t i = (size_t)blockIdx.x * blockDim.x + threadIdx.x; i < n4;
         i += (size_t)gridDim.x * blockDim.x) {
        float4 v = reinterpret_cast<const float4*>(src)[i];
        float4 o;
        o.x = __uint_as_float(tf32_rna(v.x));
        o.y = __uint_as_float(tf32_rna(v.y));
        o.z = __uint_as_float(tf32_rna(v.z));
        o.w = __uint_as_float(tf32_rna(v.w));
        reinterpret_cast<float4*>(dst)[i] = o;
    }
}

// async-copy one BC_ x DIM_ f32 tile into padded smem (16B per cp.async).
__device__ __forceinline__ void cpasync_tile(float* dst, const float* __restrict__ src,
                                             int stride, int tid) {
    unsigned dbase = (unsigned)__cvta_generic_to_shared(dst);
    #pragma unroll
    for (int i = 0; i < (BC_ * DIM_ / 4) / NTHREADS; i++) {
        int idx = i * NTHREADS + tid;
        int r = idx >> 5;
        int c = (idx & 31) << 2;
        unsigned d = dbase + (unsigned)(r * stride + c) * 4u;
        const float* s = src + (size_t)r * DIM_ + c;
        asm volatile("cp.async.cg.shared.global [%0], [%1], 16;\n" :: "r"(d), "l"(s));
    }
}
__device__ __forceinline__ void cp_commit() {
    asm volatile("cp.async.commit_group;\n" ::: "memory");
}
__device__ __forceinline__ void cp_wait1() {
    asm volatile("cp.async.wait_group 1;\n" ::: "memory");
}

__global__ __launch_bounds__(NTHREADS, 2)
void fa_tf32_kernel(const float* __restrict__ Q, float* __restrict__ Out) {
    extern __shared__ float smem[];
    float* Ksm = smem;                    // BC_ x KSTRIDE
    float* Vsm = Ksm + BC_ * KSTRIDE;     // BC_ x VSTRIDE

    const int tid  = threadIdx.x;
    const int warp = tid >> 5;
    const int lane = tid & 31;
    const int g    = lane >> 2;   // groupID (row within fragment)
    const int q4   = lane & 3;    // threadID_in_group

    const int bh = blockIdx.y;
    const int qt = blockIdx.x;
    const size_t base = (size_t)bh * NSEQ_ * DIM_;
    const float* Qg = Q + base + (size_t)qt * BR_ * DIM_;
    const float* Kg = g_kc + base;
    const float* Vg = g_vc + base;

    // ---- prologue: start K(0), V(0) async; load Q A-frags into registers ----
    cpasync_tile(Ksm, Kg, KSTRIDE, tid); cp_commit();   // group: K0
    cpasync_tile(Vsm, Vg, VSTRIDE, tid); cp_commit();   // group: V0

    // fold (1/sqrt(d)) * log2(e) into Q so scores are directly in exp2 domain
    const float qscale = 1.4426950408889634f * 0.08838834764831845f;
    unsigned Qa[16][4];                        // 16 k-steps x m16k8 A-frag
    {
        const float* qr0 = Qg + (size_t)(warp * 16 + g) * DIM_;
        const float* qr1 = qr0 + 8 * DIM_;
        #pragma unroll
        for (int k = 0; k < 16; k++) {
            int c = k * 8 + q4;
            Qa[k][0] = tf32_rna(qr0[c] * qscale);
            Qa[k][1] = tf32_rna(qr1[c] * qscale);
            Qa[k][2] = tf32_rna(qr0[c + 4] * qscale);
            Qa[k][3] = tf32_rna(qr1[c + 4] * qscale);
        }
    }

    cp_wait1();        // K0 arrived (V0 may still be in flight)
    __syncthreads();   // loop invariant: Kbuf ready+visible, V(t) pending <=1 group

    // ---- accumulators ----
    float Sa[8][4];    // S: 16 rows x 64 cols per warp
    float Oa[16][4];   // O: 16 rows x 128 cols per warp
    #pragma unroll
    for (int n = 0; n < 16; n++) {
        Oa[n][0] = 0.f; Oa[n][1] = 0.f; Oa[n][2] = 0.f; Oa[n][3] = 0.f;
    }
    float m0 = -INFINITY, m1 = -INFINITY;   // running row max (rows g, g+8)
    float l0 = 0.f, l1 = 0.f;               // running row sum

    const unsigned FULL = 0xffffffffu;

    #pragma unroll 1
    for (int t = 0; t < NTILES; ++t) {
        // ================= S = Q @ K^T (16x64 per warp) =================
        #pragma unroll
        for (int n = 0; n < 8; n++) {
            Sa[n][0] = 0.f; Sa[n][1] = 0.f; Sa[n][2] = 0.f; Sa[n][3] = 0.f;
        }
        #pragma unroll 4
        for (int k = 0; k < 16; k++) {
            const int kc = k * 8 + q4;
            #pragma unroll
            for (int n = 0; n < 8; n++) {
                const float* kb = Ksm + (n * 8 + g) * KSTRIDE + kc;
                unsigned b0 = __float_as_uint(kb[0]);
                unsigned b1 = __float_as_uint(kb[4]);
                mma_tf32(Sa[n][0], Sa[n][1], Sa[n][2], Sa[n][3],
                         Qa[k][0], Qa[k][1], Qa[k][2], Qa[k][3], b0, b1);
            }
        }

        __syncthreads();   // all warps finished reading Kbuf
        if (t + 1 < NTILES)
            cpasync_tile(Ksm, Kg + (size_t)(t + 1) * BC_ * DIM_, KSTRIDE, tid);
        cp_commit();       // group: K(t+1) (possibly empty on last iter)
        cp_wait1();        // V(t) arrived (K(t+1) still in flight)
        __syncthreads();   // Vbuf visible to all warps

        // ================= online softmax (exp2 domain) =================
        float mx0 = Sa[0][0], mx1 = Sa[0][2];
        #pragma unroll
        for (int n = 0; n < 8; n++) {
            mx0 = fmaxf(mx0, fmaxf(Sa[n][0], Sa[n][1]));
            mx1 = fmaxf(mx1, fmaxf(Sa[n][2], Sa[n][3]));
        }
        mx0 = fmaxf(mx0, __shfl_xor_sync(FULL, mx0, 1));
        mx0 = fmaxf(mx0, __shfl_xor_sync(FULL, mx0, 2));
        mx1 = fmaxf(mx1, __shfl_xor_sync(FULL, mx1, 1));
        mx1 = fmaxf(mx1, __shfl_xor_sync(FULL, mx1, 2));

        float mn0 = fmaxf(m0, mx0), mn1 = fmaxf(m1, mx1);
        float al0 = exp2f(m0 - mn0);   // exp2f(-inf)=0 on first tile
        float al1 = exp2f(m1 - mn1);
        m0 = mn0; m1 = mn1;

        float rs0 = 0.f, rs1 = 0.f;
        #pragma unroll
        for (int n = 0; n < 8; n++) {
            float p0 = exp2f(Sa[n][0] - mn0);
            float p1 = exp2f(Sa[n][1] - mn0);
            float p2 = exp2f(Sa[n][2] - mn1);
            float p3 = exp2f(Sa[n][3] - mn1);
            rs0 += p0 + p1;
            rs1 += p2 + p3;
            Sa[n][0] = __uint_as_float(tf32_rna(p0));
            Sa[n][1] = __uint_as_float(tf32_rna(p1));
            Sa[n][2] = __uint_as_float(tf32_rna(p2));
            Sa[n][3] = __uint_as_float(tf32_rna(p3));
        }
        rs0 += __shfl_xor_sync(FULL, rs0, 1);
        rs0 += __shfl_xor_sync(FULL, rs0, 2);
        rs1 += __shfl_xor_sync(FULL, rs1, 1);
        rs1 += __shfl_xor_sync(FULL, rs1, 2);
        l0 = al0 * l0 + rs0;
        l1 = al1 * l1 + rs1;

        #pragma unroll
        for (int n = 0; n < 16; n++) {
            Oa[n][0] *= al0; Oa[n][1] *= al0;
            Oa[n][2] *= al1; Oa[n][3] *= al1;
        }

        // ================= O += P @ V (overlaps K(t+1) fetch) =================
        const int s0 = (lane & ~3) | (q4 >> 1);  // quad lane holding cols {q4}
        const int s1 = s0 + 2;                   // quad lane holding cols {q4+4}
        const bool odd = (q4 & 1);
        #pragma unroll
        for (int kt = 0; kt < 8; kt++) {
            // C-frag (rows g,g+8 x cols 2q,2q+1) -> A-frag (cols q4, q4+4) via quad shuffles
            float c0 = Sa[kt][0], c1 = Sa[kt][1], c2 = Sa[kt][2], c3 = Sa[kt][3];
            float x0 = __shfl_sync(FULL, c0, s0);
            float x1 = __shfl_sync(FULL, c1, s0);
            float x2 = __shfl_sync(FULL, c2, s0);
            float x3 = __shfl_sync(FULL, c3, s0);
            float y0 = __shfl_sync(FULL, c0, s1);
            float y1 = __shfl_sync(FULL, c1, s1);
            float y2 = __shfl_sync(FULL, c2, s1);
            float y3 = __shfl_sync(FULL, c3, s1);
            unsigned pa0 = __float_as_uint(odd ? x1 : x0);  // row g,   col q4
            unsigned pa1 = __float_as_uint(odd ? x3 : x2);  // row g+8, col q4
            unsigned pa2 = __float_as_uint(odd ? y1 : y0);  // row g,   col q4+4
            unsigned pa3 = __float_as_uint(odd ? y3 : y2);  // row g+8, col q4+4
            const float* vb0 = Vsm + (kt * 8 + q4) * VSTRIDE + g;
            const float* vb1 = vb0 + 4 * VSTRIDE;
            #pragma unroll
            for (int n = 0; n < 16; n++) {
                unsigned b0 = __float_as_uint(vb0[n * 8]);
                unsigned b1 = __float_as_uint(vb1[n * 8]);
                mma_tf32(Oa[n][0], Oa[n][1], Oa[n][2], Oa[n][3], pa0, pa1, pa2, pa3, b0, b1);
            }
        }

        __syncthreads();   // all warps finished reading Vbuf
        if (t + 1 < NTILES)
            cpasync_tile(Vsm, Vg + (size_t)(t + 1) * BC_ * DIM_, VSTRIDE, tid);
        cp_commit();       // group: V(t+1) (possibly empty on last iter)
        cp_wait1();        // K(t+1) arrived (V(t+1) still in flight)
        __syncthreads();   // Kbuf visible -> loop invariant restored
    }

    // ================= epilogue: O / l =================
    const float inv0 = 1.0f / l0;
    const float inv1 = 1.0f / l1;
    float* Og = Out + base + (size_t)qt * BR_ * DIM_;
    const int r0 = warp * 16 + g;
    const int r1 = r0 + 8;
    #pragma unroll
    for (int n = 0; n < 16; n++) {
        float2 v0 = make_float2(Oa[n][0] * inv0, Oa[n][1] * inv0);
        float2 v1 = make_float2(Oa[n][2] * inv1, Oa[n][3] * inv1);
        *reinterpret_cast<float2*>(Og + (size_t)r0 * DIM_ + n * 8 + 2 * q4) = v0;
        *reinterpret_cast<float2*>(Og + (size_t)r1 * DIM_ + n * 8 + 2 * q4) = v1;
    }
}

extern "C" void kernel_launch(void* const* d_in, const int* in_sizes, int n_in,
                              void* d_out, int out_size) {
    const float* Q = (const float*)d_in[0];
    const float* K = (const float*)d_in[1];
    const float* V = (const float*)d_in[2];
    float* O = (float*)d_out;

    // pre-pass: unbiased tf32 rounding of K and V into static scratch
    float *kc_ptr = nullptr, *vc_ptr = nullptr;
    cudaGetSymbolAddress((void**)&kc_ptr, g_kc);
    cudaGetSymbolAddress((void**)&vc_ptr, g_vc);
    conv_tf32_kernel<<<2048, 256>>>(K, kc_ptr);
    conv_tf32_kernel<<<2048, 256>>>(V, vc_ptr);

    const size_t smem_bytes =
        (size_t)(BC_ * KSTRIDE + BC_ * VSTRIDE) * sizeof(float);  // 68,608 B -> 2 CTAs/SM
    cudaFuncSetAttribute(fa_tf32_kernel, cudaFuncAttributeMaxDynamicSharedMemorySize,
                         (int)smem_bytes);

    dim3 grid(NSEQ_ / BR_, BH_);  // (64, 64): same-bh CTAs adjacent -> K/V L2 reuse
    fa_tf32_kernel<<<grid, NTHREADS, smem_bytes>>>(Q, O);
}

// round 15
// speedup vs baseline: 1.0291x; 1.0291x over previous
#include <cuda_runtime.h>
#include <cuda_bf16.h>

// Problem constants (fixed by setup_inputs): B=4, H=16, N=4096, d=128.
#define BH_      64
#define NSEQ_    4096
#define DIM_     128
#define BR_      128         // Q rows per CTA
#define BC_      128         // KV rows per tile
#define KSTRIDE  132         // floats per K smem row (pad 4 -> conflict-free B-frag loads)
#define VSTRIDE  136         // floats per V smem row (pad 8 -> conflict-free B-frag loads)
#define PSTRIDE  132         // floats per P smem row (conflict-free A-frag loads)
#define NTHREADS 256         // 8 warps, each owns 16 Q rows
#define NTILES   (NSEQ_ / BC_)

// Pre-converted (tf32-rna) copies of K and V. 128MB each — static device scratch.
__device__ float g_kc[(size_t)BH_ * NSEQ_ * DIM_];
__device__ float g_vc[(size_t)BH_ * NSEQ_ * DIM_];

__device__ __forceinline__ unsigned tf32_rna(float x) {
    unsigned u;
    asm("cvt.rna.tf32.f32 %0, %1;" : "=r"(u) : "f"(x));
    return u;
}

__device__ __forceinline__ void mma_tf32(float* d,
                                         unsigned a0, unsigned a1, unsigned a2, unsigned a3,
                                         unsigned b0, unsigned b1) {
    asm("mma.sync.aligned.m16n8k8.row.col.f32.tf32.tf32.f32 "
        "{%0,%1,%2,%3}, {%4,%5,%6,%7}, {%8,%9}, {%0,%1,%2,%3};\n"
        : "+f"(d[0]), "+f"(d[1]), "+f"(d[2]), "+f"(d[3])
        : "r"(a0), "r"(a1), "r"(a2), "r"(a3), "r"(b0), "r"(b1));
}

// ---------------- pre-pass: rna-convert one array (float4 grid-stride) ----------------
__global__ void conv_tf32_kernel(const float* __restrict__ src, float* __restrict__ dst) {
    const size_t n4 = (size_t)BH_ * NSEQ_ * DIM_ / 4;
    for (size_t i = (size_t)blockIdx.x * blockDim.x + threadIdx.x; i < n4;
         i += (size_t)gridDim.x * blockDim.x) {
        float4 v = reinterpret_cast<const float4*>(src)[i];
        float4 o;
        o.x = __uint_as_float(tf32_rna(v.x));
        o.y = __uint_as_float(tf32_rna(v.y));
        o.z = __uint_as_float(tf32_rna(v.z));
        o.w = __uint_as_float(tf32_rna(v.w));
        reinterpret_cast<float4*>(dst)[i] = o;
    }
}

// async-copy one BC_ x DIM_ f32 tile into padded smem (16B per cp.async).
__device__ __forceinline__ void cpasync_tile(float* dst, const float* __restrict__ src,
                                             int stride, int tid) {
    unsigned dbase = (unsigned)__cvta_generic_to_shared(dst);
    #pragma unroll
    for (int i = 0; i < (BC_ * DIM_ / 4) / NTHREADS; i++) {
        int idx = i * NTHREADS + tid;
        int r = idx >> 5;
        int c = (idx & 31) << 2;
        unsigned d = dbase + (unsigned)(r * stride + c) * 4u;
        const float* s = src + (size_t)r * DIM_ + c;
        asm volatile("cp.async.cg.shared.global [%0], [%1], 16;\n" :: "r"(d), "l"(s));
    }
}
__device__ __forceinline__ void cp_commit() {
    asm volatile("cp.async.commit_group;\n" ::: "memory");
}
__device__ __forceinline__ void cp_wait0() {
    asm volatile("cp.async.wait_group 0;\n" ::: "memory");
}
__device__ __forceinline__ void cp_wait1() {
    asm volatile("cp.async.wait_group 1;\n" ::: "memory");
}

__global__ __launch_bounds__(NTHREADS, 1)
void fa_tf32_kernel(const float* __restrict__ Q, float* __restrict__ Out) {
    extern __shared__ float smem[];
    float* Ksm = smem;                    // BC_ x KSTRIDE
    float* Vsm = Ksm + BC_ * KSTRIDE;     // BC_ x VSTRIDE
    float* Ps  = Vsm + BC_ * VSTRIDE;     // BR_ x PSTRIDE (per-warp-private rows)

    const int tid  = threadIdx.x;
    const int warp = tid >> 5;
    const int lane = tid & 31;
    const int g    = lane >> 2;   // groupID (row within fragment)
    const int q4   = lane & 3;    // threadID_in_group

    const int bh = blockIdx.y;
    const int qt = blockIdx.x;
    const size_t base = (size_t)bh * NSEQ_ * DIM_;
    const float* Qg = Q + base + (size_t)qt * BR_ * DIM_;
    const float* Kg = g_kc + base;
    const float* Vg = g_vc + base;

    // ---- prologue: K0 fetch; Q A-frags into registers ----
    cpasync_tile(Ksm, Kg, KSTRIDE, tid); cp_commit();       // pending: [K0]

    const float qscale = 1.4426950408889634f * 0.08838834764831845f; // log2e/sqrt(d)
    unsigned Qa[16][4];                        // 16 k-steps x m16k8 A-frag
    {
        const float* qr0 = Qg + (size_t)(warp * 16 + g) * DIM_;
        const float* qr1 = qr0 + 8 * DIM_;
        #pragma unroll
        for (int k = 0; k < 16; k++) {
            int c = k * 8 + q4;
            Qa[k][0] = tf32_rna(qr0[c] * qscale);
            Qa[k][1] = tf32_rna(qr1[c] * qscale);
            Qa[k][2] = tf32_rna(qr0[c + 4] * qscale);
            Qa[k][3] = tf32_rna(qr1[c + 4] * qscale);
        }
    }

    cp_wait0();        // K0 arrived
    __syncthreads();

    // ---- S(0) = Q @ K0^T (16x128 per warp), plain k-outer/n-inner ----
    float Sa[16][4];
    #pragma unroll
    for (int n = 0; n < 16; n++) {
        Sa[n][0] = 0.f; Sa[n][1] = 0.f; Sa[n][2] = 0.f; Sa[n][3] = 0.f;
    }
    #pragma unroll 4
    for (int k = 0; k < 16; k++) {
        const int kc = k * 8 + q4;
        #pragma unroll
        for (int n = 0; n < 16; n++) {
            const float* kb = Ksm + (n * 8 + g) * KSTRIDE + kc;
            mma_tf32(Sa[n], Qa[k][0], Qa[k][1], Qa[k][2], Qa[k][3],
                     __float_as_uint(kb[0]), __float_as_uint(kb[4]));
        }
    }
    __syncthreads();   // all warps done reading K0

    cpasync_tile(Ksm, Kg + (size_t)BC_ * DIM_, KSTRIDE, tid); cp_commit(); // [K1]
    cpasync_tile(Vsm, Vg, VSTRIDE, tid); cp_commit();                       // [K1, V0]

    float Oa[16][4];
    #pragma unroll
    for (int n = 0; n < 16; n++) {
        Oa[n][0] = 0.f; Oa[n][1] = 0.f; Oa[n][2] = 0.f; Oa[n][3] = 0.f;
    }
    float m0 = -INFINITY, m1 = -INFINITY;   // running row max (rows g, g+8)
    float l0 = 0.f, l1 = 0.f;               // running row sum
    const unsigned FULL = 0xffffffffu;

    float* Pw0 = Ps + (warp * 16 + g) * PSTRIDE;       // this thread's P row g
    float* Pw1 = Pw0 + 8 * PSTRIDE;                    // row g+8

    // Loop invariant at iter t entry: Sa = raw S(t); pending = [K(t+1), V(t)].
    #pragma unroll 1
    for (int t = 0; t < NTILES; ++t) {
        const bool has_next = (t + 1 < NTILES);

        cp_wait1();        // K(t+1) arrived (V(t) may still pend)
        __syncthreads();   // Kbuf visible; all warps past previous Vsm reads

        // ---- phase (a): row max + rescale factors ----
        float mx0 = Sa[0][0], mx1 = Sa[0][2];
        #pragma unroll
        for (int n = 0; n < 16; n++) {
            mx0 = fmaxf(mx0, fmaxf(Sa[n][0], Sa[n][1]));
            mx1 = fmaxf(mx1, fmaxf(Sa[n][2], Sa[n][3]));
        }
        mx0 = fmaxf(mx0, __shfl_xor_sync(FULL, mx0, 1));
        mx0 = fmaxf(mx0, __shfl_xor_sync(FULL, mx0, 2));
        mx1 = fmaxf(mx1, __shfl_xor_sync(FULL, mx1, 1));
        mx1 = fmaxf(mx1, __shfl_xor_sync(FULL, mx1, 2));
        float mn0 = fmaxf(m0, mx0), mn1 = fmaxf(m1, mx1);
        float al0 = exp2f(m0 - mn0);   // exp2f(-inf)=0 on first tile
        float al1 = exp2f(m1 - mn1);
        m0 = mn0; m1 = mn1;
        float rs0 = 0.f, rs1 = 0.f;

        // ---- phase (b): fused softmax(t)->P-smem  +  S(t+1) gemm (chunk pairs) ----
        #pragma unroll
        for (int np = 0; np < 8; np++) {
            float t0[4] = {0.f, 0.f, 0.f, 0.f};
            float t1[4] = {0.f, 0.f, 0.f, 0.f};
            if (has_next) {
                const float* kb0 = Ksm + (np * 16 + g) * KSTRIDE + q4;
                const float* kb1 = kb0 + 8 * KSTRIDE;
                #pragma unroll
                for (int k = 0; k < 16; k++) {
                    mma_tf32(t0, Qa[k][0], Qa[k][1], Qa[k][2], Qa[k][3],
                             __float_as_uint(kb0[k * 8]), __float_as_uint(kb0[k * 8 + 4]));
                    mma_tf32(t1, Qa[k][0], Qa[k][1], Qa[k][2], Qa[k][3],
                             __float_as_uint(kb1[k * 8]), __float_as_uint(kb1[k * 8 + 4]));
                }
            }
            // softmax chunks 2np, 2np+1 (ILP against the MMA chains above)
            #pragma unroll
            for (int c = 0; c < 2; c++) {
                const int n = np * 2 + c;
                float p0 = exp2f(Sa[n][0] - mn0);
                float p1 = exp2f(Sa[n][1] - mn0);
                float p2 = exp2f(Sa[n][2] - mn1);
                float p3 = exp2f(Sa[n][3] - mn1);
                rs0 += p0 + p1;
                rs1 += p2 + p3;
                float2 w0 = make_float2(__uint_as_float(tf32_rna(p0)),
                                        __uint_as_float(tf32_rna(p1)));
                float2 w1 = make_float2(__uint_as_float(tf32_rna(p2)),
                                        __uint_as_float(tf32_rna(p3)));
                *reinterpret_cast<float2*>(Pw0 + n * 8 + 2 * q4) = w0;
                *reinterpret_cast<float2*>(Pw1 + n * 8 + 2 * q4) = w1;
                float* dst = c ? t1 : t0;
                if (has_next) {
                    Sa[n][0] = dst[0]; Sa[n][1] = dst[1];
                    Sa[n][2] = dst[2]; Sa[n][3] = dst[3];
                }
                // O rescale sprinkled through the fused phase
                Oa[n][0] *= al0; Oa[n][1] *= al0;
                Oa[n][2] *= al1; Oa[n][3] *= al1;
            }
        }
        rs0 += __shfl_xor_sync(FULL, rs0, 1);
        rs0 += __shfl_xor_sync(FULL, rs0, 2);
        rs1 += __shfl_xor_sync(FULL, rs1, 1);
        rs1 += __shfl_xor_sync(FULL, rs1, 2);
        l0 = al0 * l0 + rs0;
        l1 = al1 * l1 + rs1;

        __syncthreads();   // all warps done reading Kbuf (S(t+1) complete)
        if (t + 2 < NTILES)
            cpasync_tile(Ksm, Kg + (size_t)(t + 2) * BC_ * DIM_, KSTRIDE, tid);
        cp_commit();       // pending: [V(t), K(t+2)]

        cp_wait1();        // V(t) arrived (K(t+2) still in flight)
        __syncthreads();   // Vsm visible; also orders P-smem writes before reads

        // ---- PV(t): O += P @ V  (P A-frags straight from smem) ----
        #pragma unroll 4
        for (int kt = 0; kt < 16; kt++) {
            const int pc = kt * 8 + q4;
            unsigned pa0 = __float_as_uint(Pw0[pc]);
            unsigned pa1 = __float_as_uint(Pw1[pc]);
            unsigned pa2 = __float_as_uint(Pw0[pc + 4]);
            unsigned pa3 = __float_as_uint(Pw1[pc + 4]);
            const float* vb0 = Vsm + (kt * 8 + q4) * VSTRIDE + g;
            const float* vb1 = vb0 + 4 * VSTRIDE;
            #pragma unroll
            for (int n = 0; n < 16; n++) {
                mma_tf32(Oa[n], pa0, pa1, pa2, pa3,
                         __float_as_uint(vb0[n * 8]), __float_as_uint(vb1[n * 8]));
            }
        }

        __syncthreads();   // all warps done reading Vsm
        if (has_next)
            cpasync_tile(Vsm, Vg + (size_t)(t + 1) * BC_ * DIM_, VSTRIDE, tid);
        cp_commit();       // pending: [K(t+2), V(t+1)]  -> invariant for t+1
    }

    // ================= epilogue: O / l =================
    const float inv0 = 1.0f / l0;
    const float inv1 = 1.0f / l1;
    float* Og = Out + base + (size_t)qt * BR_ * DIM_;
    const int r0 = warp * 16 + g;
    const int r1 = r0 + 8;
    #pragma unroll
    for (int n = 0; n < 16; n++) {
        float2 v0 = make_float2(Oa[n][0] * inv0, Oa[n][1] * inv0);
        float2 v1 = make_float2(Oa[n][2] * inv1, Oa[n][3] * inv1);
        *reinterpret_cast<float2*>(Og + (size_t)r0 * DIM_ + n * 8 + 2 * q4) = v0;
        *reinterpret_cast<float2*>(Og + (size_t)r1 * DIM_ + n * 8 + 2 * q4) = v1;
    }
}

extern "C" void kernel_launch(void* const* d_in, const int* in_sizes, int n_in,
                              void* d_out, int out_size) {
    const float* Q = (const float*)d_in[0];
    const float* K = (const float*)d_in[1];
    const float* V = (const float*)d_in[2];
    float* O = (float*)d_out;

    // pre-pass: unbiased tf32 rounding of K and V into static scratch (~75us)
    float *kc_ptr = nullptr, *vc_ptr = nullptr;
    cudaGetSymbolAddress((void**)&kc_ptr, g_kc);
    cudaGetSymbolAddress((void**)&vc_ptr, g_vc);
    conv_tf32_kernel<<<2048, 256>>>(K, kc_ptr);
    conv_tf32_kernel<<<2048, 256>>>(V, vc_ptr);

    const size_t smem_bytes =
        (size_t)(BC_ * KSTRIDE + BC_ * VSTRIDE + BR_ * PSTRIDE) * sizeof(float); // 204800 B
    cudaFuncSetAttribute(fa_tf32_kernel, cudaFuncAttributeMaxDynamicSharedMemorySize,
                         (int)smem_bytes);

    dim3 grid(NSEQ_ / BR_, BH_);  // (32, 64): same-bh CTAs adjacent -> K/V L2 reuse
    fa_tf32_kernel<<<grid, NTHREADS, smem_bytes>>>(Q, O);
}